// round 2
// baseline (speedup 1.0000x reference)
#include <cuda_runtime.h>
#include <cstdint>

#define D_MODEL 1024
#define N_HEADS 16
#define HEAD_K  64
#define FF_DIM_ 4096
#define BATCH_  2
#define SEQ_    2048
#define M_TOT   (BATCH_*SEQ_)   // 4096

// ---------------- scratch (device globals: alloc-guard compliant) ----------------
__device__ float g_q  [(size_t)M_TOT * D_MODEL];   // [B,H,S,dk]
__device__ float g_k  [(size_t)M_TOT * D_MODEL];
__device__ float g_v  [(size_t)M_TOT * D_MODEL];
__device__ float g_att[(size_t)M_TOT * D_MODEL];   // [B,S,H*dk]
__device__ float g_x1 [(size_t)M_TOT * D_MODEL];   // x + attn_out
__device__ float g_h  [(size_t)M_TOT * FF_DIM_];   // relu(ff1)

// ---------------- generic SGEMM: C[M,N] = A[M,K] * W[N,K]^T (+epilogue) ----------
// MODE 0: scatter into [B,H,S,dk] (QKV)
// MODE 1: out = acc + bias + res   (Wo residual / FF2 residual)
// MODE 2: out = relu(acc + bias)   (FF1)
template<int MODE>
__global__ void __launch_bounds__(256) gemm_k(
    const float* __restrict__ A, const float* __restrict__ W,
    const float* __restrict__ bias, const float* __restrict__ res,
    float* __restrict__ out, int Kd)
{
    __shared__ float As[8][128];
    __shared__ float Bs[8][128];
    const int t  = threadIdx.x;
    const int tx = t & 15, ty = t >> 4;
    const int bm = blockIdx.y << 7, bn = blockIdx.x << 7;
    const int N  = gridDim.x << 7;

    float acc[8][8];
#pragma unroll
    for (int i = 0; i < 8; i++)
#pragma unroll
        for (int j = 0; j < 8; j++) acc[i][j] = 0.f;

    const int lrow = t >> 1;
    const int lk   = (t & 1) << 2;
    const float* Ap = A + (size_t)(bm + lrow) * Kd + lk;
    const float* Wp = W + (size_t)(bn + lrow) * Kd + lk;

    for (int k0 = 0; k0 < Kd; k0 += 8) {
        float4 av = *(const float4*)(Ap + k0);
        float4 wv = *(const float4*)(Wp + k0);
        As[lk+0][lrow] = av.x; As[lk+1][lrow] = av.y;
        As[lk+2][lrow] = av.z; As[lk+3][lrow] = av.w;
        Bs[lk+0][lrow] = wv.x; Bs[lk+1][lrow] = wv.y;
        Bs[lk+2][lrow] = wv.z; Bs[lk+3][lrow] = wv.w;
        __syncthreads();
#pragma unroll
        for (int k = 0; k < 8; k++) {
            float4 a0 = *(const float4*)&As[k][ty << 3];
            float4 a1 = *(const float4*)&As[k][(ty << 3) + 4];
            float4 b0 = *(const float4*)&Bs[k][tx << 3];
            float4 b1 = *(const float4*)&Bs[k][(tx << 3) + 4];
            float ar[8] = {a0.x, a0.y, a0.z, a0.w, a1.x, a1.y, a1.z, a1.w};
            float br[8] = {b0.x, b0.y, b0.z, b0.w, b1.x, b1.y, b1.z, b1.w};
#pragma unroll
            for (int i = 0; i < 8; i++)
#pragma unroll
                for (int j = 0; j < 8; j++)
                    acc[i][j] = fmaf(ar[i], br[j], acc[i][j]);
        }
        __syncthreads();
    }

#pragma unroll
    for (int i = 0; i < 8; i++) {
        const int row = bm + (ty << 3) + i;
#pragma unroll
        for (int j4 = 0; j4 < 2; j4++) {
            const int col = bn + (tx << 3) + (j4 << 2);
            float4 v;
            v.x = acc[i][(j4 << 2) + 0] + bias[col + 0];
            v.y = acc[i][(j4 << 2) + 1] + bias[col + 1];
            v.z = acc[i][(j4 << 2) + 2] + bias[col + 2];
            v.w = acc[i][(j4 << 2) + 3] + bias[col + 3];
            if (MODE == 0) {
                const int b = row >> 11, s = row & 2047;
                const int h = col >> 6,  kk = col & 63;
                float* dst = out + ((((size_t)(b * N_HEADS + h)) * SEQ_ + s) << 6) + kk;
                *(float4*)dst = v;
            } else if (MODE == 1) {
                const float4 rv = *(const float4*)(res + (size_t)row * N + col);
                v.x += rv.x; v.y += rv.y; v.z += rv.z; v.w += rv.w;
                *(float4*)(out + (size_t)row * N + col) = v;
            } else {
                v.x = fmaxf(v.x, 0.f); v.y = fmaxf(v.y, 0.f);
                v.z = fmaxf(v.z, 0.f); v.w = fmaxf(v.w, 0.f);
                *(float4*)(out + (size_t)row * N + col) = v;
            }
        }
    }
}

// ---------------- causal flash attention, fp32 -----------------------------------
// 64 q-rows per block, 64-key tiles, head dim 64. 256 threads:
// thread (r = t>>2, c = t&3): owns q-row r; score columns jj = 4*j + c (j=0..15);
// output dims d = c*16 .. c*16+15. Row stride 68 floats (bank-conflict-free-ish).
#define AS_ 68
#define ATT_SMEM (3 * 64 * AS_ * 4)   // sq, sk(/p), sv = 52224 bytes

__global__ void __launch_bounds__(256) attn_k()
{
    extern __shared__ float smem[];
    float* sq = smem;
    float* sk = smem + 64 * AS_;       // reused as P after scores
    float* sv = smem + 2 * 64 * AS_;

    const int t  = threadIdx.x;
    const int r  = t >> 2, c = t & 3;
    const int qb = blockIdx.x, bh = blockIdx.y;
    const size_t base = (size_t)bh * SEQ_ * 64;

    // load q tile
    {
        const float4* src = (const float4*)(g_q + base + (size_t)(qb * 64 + r) * 64) + (c << 2);
        float4* dst = (float4*)(sq + r * AS_) + (c << 2);
#pragma unroll
        for (int i = 0; i < 4; i++) dst[i] = src[i];
    }

    float m = -1e30f, l = 0.f;
    float o[16];
#pragma unroll
    for (int i = 0; i < 16; i++) o[i] = 0.f;
    const int qi = (qb << 6) + r;

    for (int kb = 0; kb <= qb; kb++) {
        __syncthreads();   // previous-iter sk/sv consumers done
        {
            const float4* ksrc = (const float4*)(g_k + base + (size_t)(kb * 64 + r) * 64) + (c << 2);
            const float4* vsrc = (const float4*)(g_v + base + (size_t)(kb * 64 + r) * 64) + (c << 2);
            float4* kdst = (float4*)(sk + r * AS_) + (c << 2);
            float4* vdst = (float4*)(sv + r * AS_) + (c << 2);
#pragma unroll
            for (int i = 0; i < 4; i++) { kdst[i] = ksrc[i]; vdst[i] = vsrc[i]; }
        }
        __syncthreads();

        // scores for columns jj = 4j + c
        float s[16];
#pragma unroll
        for (int j = 0; j < 16; j++) s[j] = 0.f;
#pragma unroll
        for (int d4 = 0; d4 < 16; d4++) {
            float4 q4 = *(const float4*)(sq + r * AS_ + (d4 << 2));
#pragma unroll
            for (int j = 0; j < 16; j++) {
                float4 k4 = *(const float4*)(sk + ((j << 2) + c) * AS_ + (d4 << 2));
                s[j] = fmaf(q4.x, k4.x, fmaf(q4.y, k4.y, fmaf(q4.z, k4.z, fmaf(q4.w, k4.w, s[j]))));
            }
        }

        // causal mask + online softmax
        float mt = -1e30f;
#pragma unroll
        for (int j = 0; j < 16; j++) {
            const int kj = (kb << 6) + (j << 2) + c;
            s[j] = (kj <= qi) ? s[j] * 0.125f : -1e30f;
            mt = fmaxf(mt, s[j]);
        }
        mt = fmaxf(mt, __shfl_xor_sync(0xffffffffu, mt, 1));
        mt = fmaxf(mt, __shfl_xor_sync(0xffffffffu, mt, 2));
        const float mnew  = fmaxf(m, mt);
        const float alpha = __expf(m - mnew);
        float p[16], lsum = 0.f;
#pragma unroll
        for (int j = 0; j < 16; j++) { p[j] = __expf(s[j] - mnew); lsum += p[j]; }
        lsum += __shfl_xor_sync(0xffffffffu, lsum, 1);
        lsum += __shfl_xor_sync(0xffffffffu, lsum, 2);
        l = l * alpha + lsum;
        m = mnew;
#pragma unroll
        for (int i = 0; i < 16; i++) o[i] *= alpha;

        __syncthreads();   // all warps done reading sk as K; now reuse as P
#pragma unroll
        for (int j = 0; j < 16; j++) sk[r * AS_ + (j << 2) + c] = p[j];
        __syncwarp();      // P row r produced entirely by this warp

#pragma unroll 8
        for (int jj = 0; jj < 64; jj++) {
            const float pv = sk[r * AS_ + jj];
            const float4* v4 = (const float4*)(sv + jj * AS_ + (c << 4));
            const float4 v0 = v4[0], v1 = v4[1], v2 = v4[2], v3 = v4[3];
            o[ 0] = fmaf(pv, v0.x, o[ 0]); o[ 1] = fmaf(pv, v0.y, o[ 1]);
            o[ 2] = fmaf(pv, v0.z, o[ 2]); o[ 3] = fmaf(pv, v0.w, o[ 3]);
            o[ 4] = fmaf(pv, v1.x, o[ 4]); o[ 5] = fmaf(pv, v1.y, o[ 5]);
            o[ 6] = fmaf(pv, v1.z, o[ 6]); o[ 7] = fmaf(pv, v1.w, o[ 7]);
            o[ 8] = fmaf(pv, v2.x, o[ 8]); o[ 9] = fmaf(pv, v2.y, o[ 9]);
            o[10] = fmaf(pv, v2.z, o[10]); o[11] = fmaf(pv, v2.w, o[11]);
            o[12] = fmaf(pv, v3.x, o[12]); o[13] = fmaf(pv, v3.y, o[13]);
            o[14] = fmaf(pv, v3.z, o[14]); o[15] = fmaf(pv, v3.w, o[15]);
        }
    }

    // write [B,S,H*dk]
    const float inv = 1.0f / l;
    const int b = bh >> 4, h = bh & 15;
    float* dst = g_att + (size_t)(b * SEQ_ + qi) * D_MODEL + (h << 6) + (c << 4);
#pragma unroll
    for (int i4 = 0; i4 < 4; i4++) {
        float4 v;
        v.x = o[i4 * 4 + 0] * inv; v.y = o[i4 * 4 + 1] * inv;
        v.z = o[i4 * 4 + 2] * inv; v.w = o[i4 * 4 + 3] * inv;
        *(float4*)(dst + (i4 << 2)) = v;
    }
}

// ---------------- launch ----------------------------------------------------------
extern "C" void kernel_launch(void* const* d_in, const int* in_sizes, int n_in,
                              void* d_out, int out_size)
{
    const float* x  = (const float*)d_in[0];
    const float* Wq = (const float*)d_in[1];
    const float* bq = (const float*)d_in[2];
    const float* Wk = (const float*)d_in[3];
    const float* bk = (const float*)d_in[4];
    const float* Wv = (const float*)d_in[5];
    const float* bv = (const float*)d_in[6];
    const float* Wo = (const float*)d_in[7];
    const float* bo = (const float*)d_in[8];
    const float* W1 = (const float*)d_in[9];
    const float* b1 = (const float*)d_in[10];
    const float* W2 = (const float*)d_in[11];
    const float* b2 = (const float*)d_in[12];
    float* out = (float*)d_out;

    float *q, *k, *v, *att, *x1, *h;
    cudaGetSymbolAddress((void**)&q,   g_q);
    cudaGetSymbolAddress((void**)&k,   g_k);
    cudaGetSymbolAddress((void**)&v,   g_v);
    cudaGetSymbolAddress((void**)&att, g_att);
    cudaGetSymbolAddress((void**)&x1,  g_x1);
    cudaGetSymbolAddress((void**)&h,   g_h);

    cudaFuncSetAttribute(attn_k, cudaFuncAttributeMaxDynamicSharedMemorySize, ATT_SMEM);

    const dim3 g8(8, 32);    // N=1024 tiles
    const dim3 g32(32, 32);  // N=4096 tiles

    gemm_k<0><<<g8, 256>>>(x,  Wq, bq, nullptr, q, D_MODEL);
    gemm_k<0><<<g8, 256>>>(x,  Wk, bk, nullptr, k, D_MODEL);
    gemm_k<0><<<g8, 256>>>(x,  Wv, bv, nullptr, v, D_MODEL);

    attn_k<<<dim3(SEQ_ / 64, BATCH_ * N_HEADS), 256, ATT_SMEM>>>();

    gemm_k<1><<<g8,  256>>>(att, Wo, bo, x,  x1,  D_MODEL);   // x + attn_out
    gemm_k<2><<<g32, 256>>>(x1,  W1, b1, nullptr, h, D_MODEL); // relu(ff1)
    gemm_k<1><<<g8,  256>>>(h,   W2, b2, x1, out, FF_DIM_);    // x1 + ff2
}

// round 8
// speedup vs baseline: 1.4745x; 1.4745x over previous
#include <cuda_runtime.h>
#include <cuda_bf16.h>
#include <cstdint>

#define D_MODEL 1024
#define N_HEADS 16
#define HEAD_K  64
#define FF_DIM_ 4096
#define BATCH_  2
#define SEQ_    2048
#define M_TOT   (BATCH_*SEQ_)   // 4096

// ======================= scratch (device globals) =================================
__device__ float g_q  [(size_t)M_TOT * D_MODEL];   // [B,H,S,dk]
__device__ float g_k  [(size_t)M_TOT * D_MODEL];
__device__ float g_v  [(size_t)M_TOT * D_MODEL];
__device__ float g_x1 [(size_t)M_TOT * D_MODEL];   // x + attn_out
// split-bf16 operands.
// A-side (activations): [R,3C] = [hi | lo | hi]
// B-side (weights):     [R,3C] = [hi | hi | lo]
__device__ __nv_bfloat16 g_xe  [(size_t)M_TOT * 3 * D_MODEL];
__device__ __nv_bfloat16 g_atte[(size_t)M_TOT * 3 * D_MODEL];
__device__ __nv_bfloat16 g_x1e [(size_t)M_TOT * 3 * D_MODEL];
__device__ __nv_bfloat16 g_he  [(size_t)M_TOT * 3 * FF_DIM_];
__device__ __nv_bfloat16 g_Wqe [(size_t)D_MODEL * 3 * D_MODEL];
__device__ __nv_bfloat16 g_Wke [(size_t)D_MODEL * 3 * D_MODEL];
__device__ __nv_bfloat16 g_Wve [(size_t)D_MODEL * 3 * D_MODEL];
__device__ __nv_bfloat16 g_Woe [(size_t)D_MODEL * 3 * D_MODEL];
__device__ __nv_bfloat16 g_W1e [(size_t)FF_DIM_ * 3 * D_MODEL];
__device__ __nv_bfloat16 g_W2e [(size_t)D_MODEL * 3 * FF_DIM_];

// ======================= helpers ==================================================
__device__ __forceinline__ uint32_t smem_u32(const void* p) {
    uint32_t a;
    asm("{ .reg .u64 t; cvta.to.shared.u64 t, %1; cvt.u32.u64 %0, t; }" : "=r"(a) : "l"(p));
    return a;
}
__device__ __forceinline__ void cp_async16(uint32_t dst, const void* src) {
    asm volatile("cp.async.cg.shared.global [%0], [%1], 16;" :: "r"(dst), "l"(src) : "memory");
}
__device__ __forceinline__ void cp_commit() {
    asm volatile("cp.async.commit_group;" ::: "memory");
}
template<int N> __device__ __forceinline__ void cp_wait() {
    asm volatile("cp.async.wait_group %0;" :: "n"(N) : "memory");
}
__device__ __forceinline__ uint32_t lds32(uint32_t addr) {
    uint32_t v;
    asm volatile("ld.shared.b32 %0, [%1];" : "=r"(v) : "r"(addr));
    return v;
}
__device__ __forceinline__ void mma_bf16(float* c, const uint32_t* a, const uint32_t* b) {
    asm volatile(
        "mma.sync.aligned.m16n8k16.row.col.f32.bf16.bf16.f32 "
        "{%0,%1,%2,%3}, {%4,%5,%6,%7}, {%8,%9}, {%0,%1,%2,%3};"
        : "+f"(c[0]), "+f"(c[1]), "+f"(c[2]), "+f"(c[3])
        : "r"(a[0]), "r"(a[1]), "r"(a[2]), "r"(a[3]), "r"(b[0]), "r"(b[1]));
}
#define SW128(off) ((off) ^ (((off) >> 3) & 0x70))

// ======================= split-bf16 helpers ======================================
// A-side: [hi | lo | hi]
__device__ __forceinline__ void store_ext(__nv_bfloat16* dst, size_t rowbase, int C, int col, float v) {
    __nv_bfloat16 hi = __float2bfloat16(v);
    float lo = v - __bfloat162float(hi);
    dst[rowbase + col]         = hi;
    dst[rowbase + C + col]     = __float2bfloat16(lo);
    dst[rowbase + 2 * C + col] = hi;
}
// B-side: [hi | hi | lo]
__device__ __forceinline__ void store_ext_b(__nv_bfloat16* dst, size_t rowbase, int C, int col, float v) {
    __nv_bfloat16 hi = __float2bfloat16(v);
    float lo = v - __bfloat162float(hi);
    dst[rowbase + col]         = hi;
    dst[rowbase + C + col]     = hi;
    dst[rowbase + 2 * C + col] = __float2bfloat16(lo);
}

// BSIDE=0: activations [hi|lo|hi]; BSIDE=1: weights [hi|hi|lo]
template<int BSIDE>
__global__ void __launch_bounds__(256) conv_ext_k(const float* __restrict__ src,
                                                  __nv_bfloat16* __restrict__ dst,
                                                  int lc, int total) {
    const int C = 1 << lc;
    for (int i = blockIdx.x * 256 + threadIdx.x; i < total; i += gridDim.x * 256) {
        const int r = i >> lc, c = i & (C - 1);
        if (BSIDE) store_ext_b(dst, (size_t)r * 3 * C, C, c, src[i]);
        else       store_ext  (dst, (size_t)r * 3 * C, C, c, src[i]);
    }
}

// ======================= mma.sync bf16 GEMM ======================================
// C[M,N] = A'[M,K3] * B'[N,K3]^T. CTA tile 128x128, BK=64 (128B rows, SW128).
// 3-stage cp.async pipeline. 8 warps (2m x 4n), warp tile 64x32, m16n8k16 frags.
// MODE 0: scatter q/k/v [B,H,S,64] fp32
// MODE 1: x1 = acc+bias+res; write fp32 + ext(A-side)
// MODE 2: h = relu(acc+bias); write ext(A-side) only
// MODE 3: out = acc+bias+res fp32
#define STAGE_BYTES 32768       // A 16KB + B 16KB
#define B_OFF 16384
#define N_STAGES 3
#define GEMM_SMEM (1024 + N_STAGES * STAGE_BYTES)

template<int MODE>
__global__ void __launch_bounds__(256, 1) tc_gemm(
    const __nv_bfloat16* __restrict__ Ae, const __nv_bfloat16* __restrict__ Be,
    const float* __restrict__ bias, const float* __restrict__ res,
    float* __restrict__ out, __nv_bfloat16* __restrict__ oute,
    int K3, int lcout)
{
    extern __shared__ char dsm[];
    const int tid  = threadIdx.x;
    const int wid  = tid >> 5;
    const int lane = tid & 31;
    const int g    = lane >> 2;          // fragment row group 0..7
    const int tg   = lane & 3;           // fragment k/col group 0..3
    const int wm   = wid & 1;            // warp m (2)
    const int wn   = wid >> 1;           // warp n (4)
    const uint32_t sb = (smem_u32(dsm) + 1023) & ~1023u;
    const int bm = blockIdx.y << 7;
    const int bn = blockIdx.x << 7;
    const int T  = K3 >> 6;

    float acc[4][4][4];
#pragma unroll
    for (int i = 0; i < 4; i++)
#pragma unroll
        for (int j = 0; j < 4; j++)
#pragma unroll
            for (int r = 0; r < 4; r++) acc[i][j][r] = 0.f;

    // ---- tile loader: 8 x cp.async 16B per thread (A 4, B 4) ----
    auto load_tile = [&](int tile, uint32_t stage) {
        const int k0 = tile << 6;
#pragma unroll
        for (int it = 0; it < 4; it++) {
            const int idx = tid + it * 256;
            const int row = idx >> 3, co = (idx & 7) << 4;
            cp_async16(stage + SW128(row * 128 + co),
                       (const char*)Ae + ((size_t)(bm + row) * K3 + k0) * 2 + co);
        }
#pragma unroll
        for (int it = 0; it < 4; it++) {
            const int idx = tid + it * 256;
            const int row = idx >> 3, co = (idx & 7) << 4;
            cp_async16(stage + B_OFF + SW128(row * 128 + co),
                       (const char*)Be + ((size_t)(bn + row) * K3 + k0) * 2 + co);
        }
        cp_commit();
    };

    load_tile(0, sb);
    load_tile(1, sb + STAGE_BYTES);
    load_tile(2, sb + 2 * STAGE_BYTES);

    const uint32_t gx = (uint32_t)(g << 4);      // swizzle xor (all frag rows ≡ g mod 8)
    const uint32_t tg4 = (uint32_t)(tg << 2);

    for (int t = 0; t < T; t++) {
        cp_wait<2>();
        __syncthreads();
        const uint32_t stage = sb + (uint32_t)(t % N_STAGES) * STAGE_BYTES;
        const uint32_t abase = stage + (uint32_t)(wm * 64 + g) * 128;
        const uint32_t bbase = stage + B_OFF + (uint32_t)(wn * 32 + g) * 128;

#pragma unroll
        for (int kk = 0; kk < 4; kk++) {
            const uint32_t kb0 = ((uint32_t)(kk * 32) + tg4) ^ gx;
            const uint32_t kb1 = ((uint32_t)(kk * 32 + 16) + tg4) ^ gx;
            uint32_t a[4][4], b[4][2];
#pragma unroll
            for (int mi = 0; mi < 4; mi++) {
                const uint32_t r0 = abase + (uint32_t)(mi * 16) * 128;
                a[mi][0] = lds32(r0 + kb0);
                a[mi][1] = lds32(r0 + 8 * 128 + kb0);
                a[mi][2] = lds32(r0 + kb1);
                a[mi][3] = lds32(r0 + 8 * 128 + kb1);
            }
#pragma unroll
            for (int ni = 0; ni < 4; ni++) {
                const uint32_t r0 = bbase + (uint32_t)(ni * 8) * 128;
                b[ni][0] = lds32(r0 + kb0);
                b[ni][1] = lds32(r0 + kb1);
            }
#pragma unroll
            for (int mi = 0; mi < 4; mi++)
#pragma unroll
                for (int ni = 0; ni < 4; ni++)
                    mma_bf16(acc[mi][ni], a[mi], b[ni]);
        }
        __syncthreads();
        if (t + 3 < T) load_tile(t + 3, stage);
    }

    // ---- epilogue ----
#pragma unroll
    for (int mi = 0; mi < 4; mi++) {
        const int r0 = bm + wm * 64 + mi * 16 + g;
#pragma unroll
        for (int rr = 0; rr < 2; rr++) {
            const int grow = r0 + rr * 8;
#pragma unroll
            for (int ni = 0; ni < 4; ni++) {
                const int gcol = bn + wn * 32 + ni * 8 + tg * 2;
                float v0 = acc[mi][ni][rr * 2 + 0] + bias[gcol];
                float v1 = acc[mi][ni][rr * 2 + 1] + bias[gcol + 1];

                if (MODE == 0) {
                    const int b_ = grow >> 11, s = grow & 2047;
                    const int h = gcol >> 6, kk = gcol & 63;
                    float* dst = out + ((((size_t)(b_ * N_HEADS + h)) * SEQ_ + s) << 6) + kk;
                    *(float2*)dst = make_float2(v0, v1);
                } else if (MODE == 1) {
                    const size_t rb = (size_t)grow * 1024 + gcol;
                    const float2 rv = *(const float2*)(res + rb);
                    v0 += rv.x; v1 += rv.y;
                    *(float2*)(out + rb) = make_float2(v0, v1);
                    const int C = 1 << lcout;
                    const size_t erb = (size_t)grow * 3 * C;
                    store_ext(oute, erb, C, gcol, v0);
                    store_ext(oute, erb, C, gcol + 1, v1);
                } else if (MODE == 2) {
                    const int C = 1 << lcout;
                    const size_t erb = (size_t)grow * 3 * C;
                    store_ext(oute, erb, C, gcol, fmaxf(v0, 0.f));
                    store_ext(oute, erb, C, gcol + 1, fmaxf(v1, 0.f));
                } else {
                    const size_t rb = (size_t)grow * 1024 + gcol;
                    const float2 rv = *(const float2*)(res + rb);
                    *(float2*)(out + rb) = make_float2(v0 + rv.x, v1 + rv.y);
                }
            }
        }
    }
}

// ======================= causal flash attention, fp32 ============================
#define AS_ 68
#define ATT_SMEM (3 * 64 * AS_ * 4)

__global__ void __launch_bounds__(256) attn_k()
{
    extern __shared__ float smem[];
    float* sq = smem;
    float* sk = smem + 64 * AS_;
    float* sv = smem + 2 * 64 * AS_;

    const int t  = threadIdx.x;
    const int r  = t >> 2, c = t & 3;
    const int qb = blockIdx.x, bh = blockIdx.y;
    const size_t base = (size_t)bh * SEQ_ * 64;

    {
        const float4* src = (const float4*)(g_q + base + (size_t)(qb * 64 + r) * 64) + (c << 2);
        float4* dst = (float4*)(sq + r * AS_) + (c << 2);
#pragma unroll
        for (int i = 0; i < 4; i++) dst[i] = src[i];
    }

    float m = -1e30f, l = 0.f;
    float o[16];
#pragma unroll
    for (int i = 0; i < 16; i++) o[i] = 0.f;
    const int qi = (qb << 6) + r;

    for (int kb = 0; kb <= qb; kb++) {
        __syncthreads();
        {
            const float4* ksrc = (const float4*)(g_k + base + (size_t)(kb * 64 + r) * 64) + (c << 2);
            const float4* vsrc = (const float4*)(g_v + base + (size_t)(kb * 64 + r) * 64) + (c << 2);
            float4* kdst = (float4*)(sk + r * AS_) + (c << 2);
            float4* vdst = (float4*)(sv + r * AS_) + (c << 2);
#pragma unroll
            for (int i = 0; i < 4; i++) { kdst[i] = ksrc[i]; vdst[i] = vsrc[i]; }
        }
        __syncthreads();

        float s[16];
#pragma unroll
        for (int j = 0; j < 16; j++) s[j] = 0.f;
#pragma unroll
        for (int d4 = 0; d4 < 16; d4++) {
            float4 q4 = *(const float4*)(sq + r * AS_ + (d4 << 2));
#pragma unroll
            for (int j = 0; j < 16; j++) {
                float4 k4 = *(const float4*)(sk + ((j << 2) + c) * AS_ + (d4 << 2));
                s[j] = fmaf(q4.x, k4.x, fmaf(q4.y, k4.y, fmaf(q4.z, k4.z, fmaf(q4.w, k4.w, s[j]))));
            }
        }

        float mt = -1e30f;
#pragma unroll
        for (int j = 0; j < 16; j++) {
            const int kj = (kb << 6) + (j << 2) + c;
            s[j] = (kj <= qi) ? s[j] * 0.125f : -1e30f;
            mt = fmaxf(mt, s[j]);
        }
        mt = fmaxf(mt, __shfl_xor_sync(0xffffffffu, mt, 1));
        mt = fmaxf(mt, __shfl_xor_sync(0xffffffffu, mt, 2));
        const float mnew  = fmaxf(m, mt);
        const float alpha = __expf(m - mnew);
        float p[16], lsum = 0.f;
#pragma unroll
        for (int j = 0; j < 16; j++) { p[j] = __expf(s[j] - mnew); lsum += p[j]; }
        lsum += __shfl_xor_sync(0xffffffffu, lsum, 1);
        lsum += __shfl_xor_sync(0xffffffffu, lsum, 2);
        l = l * alpha + lsum;
        m = mnew;
#pragma unroll
        for (int i = 0; i < 16; i++) o[i] *= alpha;

        __syncthreads();
#pragma unroll
        for (int j = 0; j < 16; j++) sk[r * AS_ + (j << 2) + c] = p[j];
        __syncwarp();

#pragma unroll 8
        for (int jj = 0; jj < 64; jj++) {
            const float pv = sk[r * AS_ + jj];
            const float4* v4 = (const float4*)(sv + jj * AS_ + (c << 4));
            const float4 v0 = v4[0], v1 = v4[1], v2 = v4[2], v3 = v4[3];
            o[ 0] = fmaf(pv, v0.x, o[ 0]); o[ 1] = fmaf(pv, v0.y, o[ 1]);
            o[ 2] = fmaf(pv, v0.z, o[ 2]); o[ 3] = fmaf(pv, v0.w, o[ 3]);
            o[ 4] = fmaf(pv, v1.x, o[ 4]); o[ 5] = fmaf(pv, v1.y, o[ 5]);
            o[ 6] = fmaf(pv, v1.z, o[ 6]); o[ 7] = fmaf(pv, v1.w, o[ 7]);
            o[ 8] = fmaf(pv, v2.x, o[ 8]); o[ 9] = fmaf(pv, v2.y, o[ 9]);
            o[10] = fmaf(pv, v2.z, o[10]); o[11] = fmaf(pv, v2.w, o[11]);
            o[12] = fmaf(pv, v3.x, o[12]); o[13] = fmaf(pv, v3.y, o[13]);
            o[14] = fmaf(pv, v3.z, o[14]); o[15] = fmaf(pv, v3.w, o[15]);
        }
    }

    // epilogue: write split-bf16 A-side operand for the Wo GEMM directly
    const float inv = 1.0f / l;
    const int b = bh >> 4, h = bh & 15;
    const int row = b * SEQ_ + qi;
    const int colbase = (h << 6) + (c << 4);
    const size_t erb = (size_t)row * 3 * D_MODEL;
#pragma unroll
    for (int i = 0; i < 16; i++)
        store_ext(g_atte, erb, D_MODEL, colbase + i, o[i] * inv);
}

// ======================= launch ==================================================
extern "C" void kernel_launch(void* const* d_in, const int* in_sizes, int n_in,
                              void* d_out, int out_size)
{
    const float* x  = (const float*)d_in[0];
    const float* Wq = (const float*)d_in[1];
    const float* bq = (const float*)d_in[2];
    const float* Wk = (const float*)d_in[3];
    const float* bk = (const float*)d_in[4];
    const float* Wv = (const float*)d_in[5];
    const float* bv = (const float*)d_in[6];
    const float* Wo = (const float*)d_in[7];
    const float* bo = (const float*)d_in[8];
    const float* W1 = (const float*)d_in[9];
    const float* b1 = (const float*)d_in[10];
    const float* W2 = (const float*)d_in[11];
    const float* b2 = (const float*)d_in[12];
    float* out = (float*)d_out;

    float *q, *k, *v, *x1;
    __nv_bfloat16 *xe, *atte, *x1e, *he, *Wqe, *Wke, *Wve, *Woe, *W1e, *W2e;
    cudaGetSymbolAddress((void**)&q,    g_q);
    cudaGetSymbolAddress((void**)&k,    g_k);
    cudaGetSymbolAddress((void**)&v,    g_v);
    cudaGetSymbolAddress((void**)&x1,   g_x1);
    cudaGetSymbolAddress((void**)&xe,   g_xe);
    cudaGetSymbolAddress((void**)&atte, g_atte);
    cudaGetSymbolAddress((void**)&x1e,  g_x1e);
    cudaGetSymbolAddress((void**)&he,   g_he);
    cudaGetSymbolAddress((void**)&Wqe,  g_Wqe);
    cudaGetSymbolAddress((void**)&Wke,  g_Wke);
    cudaGetSymbolAddress((void**)&Wve,  g_Wve);
    cudaGetSymbolAddress((void**)&Woe,  g_Woe);
    cudaGetSymbolAddress((void**)&W1e,  g_W1e);
    cudaGetSymbolAddress((void**)&W2e,  g_W2e);

    cudaFuncSetAttribute(tc_gemm<0>, cudaFuncAttributeMaxDynamicSharedMemorySize, GEMM_SMEM);
    cudaFuncSetAttribute(tc_gemm<1>, cudaFuncAttributeMaxDynamicSharedMemorySize, GEMM_SMEM);
    cudaFuncSetAttribute(tc_gemm<2>, cudaFuncAttributeMaxDynamicSharedMemorySize, GEMM_SMEM);
    cudaFuncSetAttribute(tc_gemm<3>, cudaFuncAttributeMaxDynamicSharedMemorySize, GEMM_SMEM);
    cudaFuncSetAttribute(attn_k, cudaFuncAttributeMaxDynamicSharedMemorySize, ATT_SMEM);

    // conversions: x is an A operand; all weights are B operands
    conv_ext_k<0><<<2048, 256>>>(x,  xe,  10, M_TOT * D_MODEL);
    conv_ext_k<1><<<2048, 256>>>(Wq, Wqe, 10, D_MODEL * D_MODEL);
    conv_ext_k<1><<<2048, 256>>>(Wk, Wke, 10, D_MODEL * D_MODEL);
    conv_ext_k<1><<<2048, 256>>>(Wv, Wve, 10, D_MODEL * D_MODEL);
    conv_ext_k<1><<<2048, 256>>>(Wo, Woe, 10, D_MODEL * D_MODEL);
    conv_ext_k<1><<<2048, 256>>>(W1, W1e, 10, FF_DIM_ * D_MODEL);
    conv_ext_k<1><<<2048, 256>>>(W2, W2e, 12, D_MODEL * FF_DIM_);

    const dim3 gN1024(D_MODEL / 128, M_TOT / 128);   // (8, 32)
    const dim3 gN4096(FF_DIM_ / 128, M_TOT / 128);   // (32, 32)

    tc_gemm<0><<<gN1024, 256, GEMM_SMEM>>>(xe, Wqe, bq, nullptr, q, nullptr, 3 * D_MODEL, 0);
    tc_gemm<0><<<gN1024, 256, GEMM_SMEM>>>(xe, Wke, bk, nullptr, k, nullptr, 3 * D_MODEL, 0);
    tc_gemm<0><<<gN1024, 256, GEMM_SMEM>>>(xe, Wve, bv, nullptr, v, nullptr, 3 * D_MODEL, 0);

    attn_k<<<dim3(SEQ_ / 64, BATCH_ * N_HEADS), 256, ATT_SMEM>>>();

    tc_gemm<1><<<gN1024, 256, GEMM_SMEM>>>(atte, Woe, bo, x, x1, x1e, 3 * D_MODEL, 10);
    tc_gemm<2><<<gN4096, 256, GEMM_SMEM>>>(x1e, W1e, b1, nullptr, nullptr, he, 3 * D_MODEL, 12);
    tc_gemm<3><<<gN1024, 256, GEMM_SMEM>>>(he, W2e, b2, x1, out, nullptr, 3 * FF_DIM_, 0);
}

// round 10
// speedup vs baseline: 3.2666x; 2.2155x over previous
#include <cuda_runtime.h>
#include <cuda_bf16.h>
#include <cstdint>

#define D_MODEL 1024
#define N_HEADS 16
#define HEAD_K  64
#define FF_DIM_ 4096
#define BATCH_  2
#define SEQ_    2048
#define M_TOT   (BATCH_*SEQ_)   // 4096

// ======================= scratch (device globals) =================================
__device__ float g_x1 [(size_t)M_TOT * D_MODEL];   // x + attn_out
// split-bf16 ext operands (A-side [hi|lo|hi], B-side [hi|hi|lo])
__device__ __nv_bfloat16 g_xe  [(size_t)M_TOT * 3 * D_MODEL];
__device__ __nv_bfloat16 g_atte[(size_t)M_TOT * 3 * D_MODEL];
__device__ __nv_bfloat16 g_x1e [(size_t)M_TOT * 3 * D_MODEL];
__device__ __nv_bfloat16 g_he  [(size_t)M_TOT * 3 * FF_DIM_];
__device__ __nv_bfloat16 g_Wqkve[(size_t)3 * D_MODEL * 3 * D_MODEL];  // rows 0..3071 B-side
__device__ __nv_bfloat16 g_Woe [(size_t)D_MODEL * 3 * D_MODEL];
__device__ __nv_bfloat16 g_W1e [(size_t)FF_DIM_ * 3 * D_MODEL];
__device__ __nv_bfloat16 g_W2e [(size_t)D_MODEL * 3 * FF_DIM_];
__device__ float g_bqkv[3 * D_MODEL];
// attention operands: hi/lo pairs. q pre-scaled by 0.125. vt is transposed [B,H,64,S].
__device__ __nv_bfloat16 g_qh [(size_t)M_TOT * 64 * N_HEADS];
__device__ __nv_bfloat16 g_ql [(size_t)M_TOT * 64 * N_HEADS];
__device__ __nv_bfloat16 g_kh [(size_t)M_TOT * 64 * N_HEADS];
__device__ __nv_bfloat16 g_kl [(size_t)M_TOT * 64 * N_HEADS];
__device__ __nv_bfloat16 g_vth[(size_t)M_TOT * 64 * N_HEADS];
__device__ __nv_bfloat16 g_vtl[(size_t)M_TOT * 64 * N_HEADS];

// ======================= helpers ==================================================
__device__ __forceinline__ uint32_t smem_u32(const void* p) {
    uint32_t a;
    asm("{ .reg .u64 t; cvta.to.shared.u64 t, %1; cvt.u32.u64 %0, t; }" : "=r"(a) : "l"(p));
    return a;
}
__device__ __forceinline__ void cp_async16(uint32_t dst, const void* src) {
    asm volatile("cp.async.cg.shared.global [%0], [%1], 16;" :: "r"(dst), "l"(src) : "memory");
}
__device__ __forceinline__ void cp_commit() {
    asm volatile("cp.async.commit_group;" ::: "memory");
}
template<int N> __device__ __forceinline__ void cp_wait() {
    asm volatile("cp.async.wait_group %0;" :: "n"(N) : "memory");
}
__device__ __forceinline__ uint32_t lds32(uint32_t addr) {
    uint32_t v;
    asm volatile("ld.shared.b32 %0, [%1];" : "=r"(v) : "r"(addr));
    return v;
}
__device__ __forceinline__ void sts32(uint32_t addr, uint32_t v) {
    asm volatile("st.shared.b32 [%0], %1;" :: "r"(addr), "r"(v) : "memory");
}
__device__ __forceinline__ void mma_bf16(float* c, const uint32_t* a, const uint32_t* b) {
    asm volatile(
        "mma.sync.aligned.m16n8k16.row.col.f32.bf16.bf16.f32 "
        "{%0,%1,%2,%3}, {%4,%5,%6,%7}, {%8,%9}, {%0,%1,%2,%3};"
        : "+f"(c[0]), "+f"(c[1]), "+f"(c[2]), "+f"(c[3])
        : "r"(a[0]), "r"(a[1]), "r"(a[2]), "r"(a[3]), "r"(b[0]), "r"(b[1]));
}
#define SW128(off) ((off) ^ (((off) >> 3) & 0x70))

__device__ __forceinline__ void split2(float v, __nv_bfloat16& hi, __nv_bfloat16& lo) {
    hi = __float2bfloat16(v);
    lo = __float2bfloat16(v - __bfloat162float(hi));
}
// A-side ext: [hi | lo | hi]
__device__ __forceinline__ void store_ext(__nv_bfloat16* dst, size_t rowbase, int C, int col, float v) {
    __nv_bfloat16 hi, lo; split2(v, hi, lo);
    dst[rowbase + col] = hi;
    dst[rowbase + C + col] = lo;
    dst[rowbase + 2 * C + col] = hi;
}
// B-side ext: [hi | hi | lo]
__device__ __forceinline__ void store_ext_b(__nv_bfloat16* dst, size_t rowbase, int C, int col, float v) {
    __nv_bfloat16 hi, lo; split2(v, hi, lo);
    dst[rowbase + col] = hi;
    dst[rowbase + C + col] = hi;
    dst[rowbase + 2 * C + col] = lo;
}

template<int BSIDE>
__global__ void __launch_bounds__(256) conv_ext_k(const float* __restrict__ src,
                                                  __nv_bfloat16* __restrict__ dst,
                                                  int lc, int total) {
    const int C = 1 << lc;
    for (int i = blockIdx.x * 256 + threadIdx.x; i < total; i += gridDim.x * 256) {
        const int r = i >> lc, c = i & (C - 1);
        if (BSIDE) store_ext_b(dst, (size_t)r * 3 * C, C, c, src[i]);
        else       store_ext  (dst, (size_t)r * 3 * C, C, c, src[i]);
    }
}

__global__ void __launch_bounds__(256) concat_bias_k(const float* __restrict__ bq,
                                                     const float* __restrict__ bk,
                                                     const float* __restrict__ bv) {
    int i = blockIdx.x * 256 + threadIdx.x;
    if (i < 1024)       g_bqkv[i] = bq[i];
    else if (i < 2048)  g_bqkv[i] = bk[i - 1024];
    else if (i < 3072)  g_bqkv[i] = bv[i - 2048];
}

// ======================= mma.sync bf16 GEMM ======================================
// C[M,N] = A'[M,K3] * B'[N,K3]^T. CTA 128x128, BK=64, SW128, 3-stage cp.async.
// MODE 0: fused QKV epilogue -> q_hi/lo (x0.125), k_hi/lo, vt_hi/lo (transposed)
// MODE 1: x1 = acc+bias+res; write fp32 + ext(A-side)
// MODE 2: h = relu(acc+bias); write ext(A-side)
// MODE 3: out = acc+bias+res fp32
#define STAGE_BYTES 32768
#define B_OFF 16384
#define N_STAGES 3
#define GEMM_SMEM (1024 + N_STAGES * STAGE_BYTES)

template<int MODE>
__global__ void __launch_bounds__(256, 1) tc_gemm(
    const __nv_bfloat16* __restrict__ Ae, const __nv_bfloat16* __restrict__ Be,
    const float* __restrict__ bias, const float* __restrict__ res,
    float* __restrict__ out, __nv_bfloat16* __restrict__ oute,
    int K3, int lcout)
{
    extern __shared__ char dsm[];
    const int tid  = threadIdx.x;
    const int wid  = tid >> 5;
    const int lane = tid & 31;
    const int g    = lane >> 2;
    const int tg   = lane & 3;
    const int wm   = wid & 1;
    const int wn   = wid >> 1;
    const uint32_t sb = (smem_u32(dsm) + 1023) & ~1023u;
    const int bm = blockIdx.y << 7;
    const int bn = blockIdx.x << 7;
    const int T  = K3 >> 6;

    float acc[4][4][4];
#pragma unroll
    for (int i = 0; i < 4; i++)
#pragma unroll
        for (int j = 0; j < 4; j++)
#pragma unroll
            for (int r = 0; r < 4; r++) acc[i][j][r] = 0.f;

    auto load_tile = [&](int tile, uint32_t stage) {
        const int k0 = tile << 6;
#pragma unroll
        for (int it = 0; it < 4; it++) {
            const int idx = tid + it * 256;
            const int row = idx >> 3, co = (idx & 7) << 4;
            cp_async16(stage + SW128(row * 128 + co),
                       (const char*)Ae + ((size_t)(bm + row) * K3 + k0) * 2 + co);
        }
#pragma unroll
        for (int it = 0; it < 4; it++) {
            const int idx = tid + it * 256;
            const int row = idx >> 3, co = (idx & 7) << 4;
            cp_async16(stage + B_OFF + SW128(row * 128 + co),
                       (const char*)Be + ((size_t)(bn + row) * K3 + k0) * 2 + co);
        }
        cp_commit();
    };

    load_tile(0, sb);
    load_tile(1, sb + STAGE_BYTES);
    load_tile(2, sb + 2 * STAGE_BYTES);

    const uint32_t gx = (uint32_t)(g << 4);
    const uint32_t tg4 = (uint32_t)(tg << 2);

    for (int t = 0; t < T; t++) {
        cp_wait<2>();
        __syncthreads();
        const uint32_t stage = sb + (uint32_t)(t % N_STAGES) * STAGE_BYTES;
        const uint32_t abase = stage + (uint32_t)(wm * 64 + g) * 128;
        const uint32_t bbase = stage + B_OFF + (uint32_t)(wn * 32 + g) * 128;

#pragma unroll
        for (int kk = 0; kk < 4; kk++) {
            const uint32_t kb0 = ((uint32_t)(kk * 32) + tg4) ^ gx;
            const uint32_t kb1 = ((uint32_t)(kk * 32 + 16) + tg4) ^ gx;
            uint32_t a[4][4], b[4][2];
#pragma unroll
            for (int mi = 0; mi < 4; mi++) {
                const uint32_t r0 = abase + (uint32_t)(mi * 16) * 128;
                a[mi][0] = lds32(r0 + kb0);
                a[mi][1] = lds32(r0 + 8 * 128 + kb0);
                a[mi][2] = lds32(r0 + kb1);
                a[mi][3] = lds32(r0 + 8 * 128 + kb1);
            }
#pragma unroll
            for (int ni = 0; ni < 4; ni++) {
                const uint32_t r0 = bbase + (uint32_t)(ni * 8) * 128;
                b[ni][0] = lds32(r0 + kb0);
                b[ni][1] = lds32(r0 + kb1);
            }
#pragma unroll
            for (int mi = 0; mi < 4; mi++)
#pragma unroll
                for (int ni = 0; ni < 4; ni++)
                    mma_bf16(acc[mi][ni], a[mi], b[ni]);
        }
        __syncthreads();
        if (t + 3 < T) load_tile(t + 3, stage);
    }

    // ---- epilogue ----
#pragma unroll
    for (int mi = 0; mi < 4; mi++) {
        const int r0 = bm + wm * 64 + mi * 16 + g;
#pragma unroll
        for (int rr = 0; rr < 2; rr++) {
            const int grow = r0 + rr * 8;
#pragma unroll
            for (int ni = 0; ni < 4; ni++) {
                const int gcol = bn + wn * 32 + ni * 8 + tg * 2;
                float v0 = acc[mi][ni][rr * 2 + 0] + bias[gcol];
                float v1 = acc[mi][ni][rr * 2 + 1] + bias[gcol + 1];

                if (MODE == 0) {
                    const int b_ = grow >> 11, s = grow & 2047;
                    if (gcol < 1024) {          // Q (prescale 0.125)
                        const int h = gcol >> 6, dk = gcol & 63;
                        const size_t idx = ((size_t)(b_ * 16 + h) * 2048 + s) * 64 + dk;
                        __nv_bfloat16 hi, lo;
                        split2(v0 * 0.125f, hi, lo); g_qh[idx] = hi;     g_ql[idx] = lo;
                        split2(v1 * 0.125f, hi, lo); g_qh[idx + 1] = hi; g_ql[idx + 1] = lo;
                    } else if (gcol < 2048) {   // K
                        const int lc = gcol - 1024;
                        const int h = lc >> 6, dk = lc & 63;
                        const size_t idx = ((size_t)(b_ * 16 + h) * 2048 + s) * 64 + dk;
                        __nv_bfloat16 hi, lo;
                        split2(v0, hi, lo); g_kh[idx] = hi;     g_kl[idx] = lo;
                        split2(v1, hi, lo); g_kh[idx + 1] = hi; g_kl[idx + 1] = lo;
                    } else {                    // V transposed [B,H,64,S]
                        const int lc = gcol - 2048;
                        const int h = lc >> 6, dk = lc & 63;
                        const size_t idx = ((size_t)(b_ * 16 + h) * 64 + dk) * 2048 + s;
                        __nv_bfloat16 hi, lo;
                        split2(v0, hi, lo); g_vth[idx] = hi;        g_vtl[idx] = lo;
                        split2(v1, hi, lo); g_vth[idx + 2048] = hi; g_vtl[idx + 2048] = lo;
                    }
                } else if (MODE == 1) {
                    const size_t rb = (size_t)grow * 1024 + gcol;
                    const float2 rv = *(const float2*)(res + rb);
                    v0 += rv.x; v1 += rv.y;
                    *(float2*)(out + rb) = make_float2(v0, v1);
                    const int C = 1 << lcout;
                    const size_t erb = (size_t)grow * 3 * C;
                    store_ext(oute, erb, C, gcol, v0);
                    store_ext(oute, erb, C, gcol + 1, v1);
                } else if (MODE == 2) {
                    const int C = 1 << lcout;
                    const size_t erb = (size_t)grow * 3 * C;
                    store_ext(oute, erb, C, gcol, fmaxf(v0, 0.f));
                    store_ext(oute, erb, C, gcol + 1, fmaxf(v1, 0.f));
                } else {
                    const size_t rb = (size_t)grow * 1024 + gcol;
                    const float2 rv = *(const float2*)(res + rb);
                    *(float2*)(out + rb) = make_float2(v0 + rv.x, v1 + rv.y);
                }
            }
        }
    }
}

// ======================= tensor-core causal flash attention ======================
// 128 threads, 4 warps x 16 q-rows. 64-key tiles, double-buffered cp.async.
// Scores: segs {(Qh,Kh),(Ql,Kh),(Qh,Kl)}; PV: segs {(Ph,Vh),(Pl,Vh),(Ph,Vl)}.
#define AQH 0
#define AQL 8192
#define AKV0 16384          // Kh, Kl, Vh, Vl each 8KB
#define AKV1 49152
#define APH 81920
#define APL 90112
#define ATT_SMEM 98304

__global__ void __launch_bounds__(128) attn_mma()
{
    extern __shared__ char sm[];
    const uint32_t sb = smem_u32(sm);
    const int tid = threadIdx.x;
    const int wr  = tid >> 5;
    const int lane = tid & 31;
    const int g  = lane >> 2;
    const int tg = lane & 3;
    const uint32_t gx = (uint32_t)(g << 4);
    const uint32_t tg4 = (uint32_t)(tg << 2);
    const int qb = blockIdx.x, bh = blockIdx.y;
    const int b_ = bh >> 4, h_ = bh & 15;

    const size_t qkb = (size_t)bh * 2048 * 64;
    const __nv_bfloat16* qh = g_qh + qkb + (size_t)qb * 4096;
    const __nv_bfloat16* ql = g_ql + qkb + (size_t)qb * 4096;
    const __nv_bfloat16* kh = g_kh + qkb;
    const __nv_bfloat16* kl = g_kl + qkb;
    const __nv_bfloat16* vth = g_vth + (size_t)bh * 64 * 2048;
    const __nv_bfloat16* vtl = g_vtl + (size_t)bh * 64 * 2048;

    // contiguous 8KB tile load (rows of 128B), SW128 swizzled
    auto ld_contig = [&](uint32_t dst, const __nv_bfloat16* src) {
#pragma unroll
        for (int it = 0; it < 4; it++) {
            const int c = tid + it * 128;
            const int row = c >> 3, co = (c & 7) << 4;
            cp_async16(dst + SW128(row * 128 + co), (const char*)src + c * 16);
        }
    };
    // Vt tile: row dk (stride 2048 elems), col window kb*64..+64
    auto ld_vt = [&](uint32_t dst, const __nv_bfloat16* src) {
#pragma unroll
        for (int it = 0; it < 4; it++) {
            const int c = tid + it * 128;
            const int row = c >> 3, co = (c & 7) << 4;
            cp_async16(dst + SW128(row * 128 + co),
                       (const char*)(src + (size_t)row * 2048) + co);
        }
    };
    auto load_kv = [&](int kb, uint32_t off) {
        ld_contig(sb + off,          kh + (size_t)kb * 4096);
        ld_contig(sb + off + 8192,   kl + (size_t)kb * 4096);
        ld_vt    (sb + off + 16384,  vth + (size_t)kb * 64);
        ld_vt    (sb + off + 24576,  vtl + (size_t)kb * 64);
    };

    ld_contig(sb + AQH, qh);
    ld_contig(sb + AQL, ql);
    load_kv(0, AKV0);
    cp_commit();

    float m2[2] = {-1e30f, -1e30f}, l2[2] = {0.f, 0.f};
    float o[8][4];
#pragma unroll
    for (int i = 0; i < 8; i++)
#pragma unroll
        for (int j = 0; j < 4; j++) o[i][j] = 0.f;

    const uint32_t arow = (uint32_t)(wr * 16 + g) * 128;

    for (int kb = 0; kb <= qb; kb++) {
        const uint32_t kvoff = (kb & 1) ? AKV1 : AKV0;
        if (kb < qb) {
            load_kv(kb + 1, (kb & 1) ? AKV0 : AKV1);
            cp_commit();
            cp_wait<1>();
        } else {
            cp_wait<0>();
        }
        __syncthreads();

        // ---- scores: 3 segs x 4 kfrags x 8 nfrags ----
        float sc[8][4];
#pragma unroll
        for (int i = 0; i < 8; i++)
#pragma unroll
            for (int j = 0; j < 4; j++) sc[i][j] = 0.f;

#pragma unroll
        for (int seg = 0; seg < 3; seg++) {
            const uint32_t ab = sb + ((seg == 1) ? AQL : AQH) + arow;
            const uint32_t bb = sb + kvoff + ((seg == 2) ? 8192u : 0u) + (uint32_t)(g * 128);
#pragma unroll
            for (int kk = 0; kk < 4; kk++) {
                const uint32_t k0 = ((uint32_t)(kk * 32) + tg4) ^ gx;
                const uint32_t k1 = ((uint32_t)(kk * 32 + 16) + tg4) ^ gx;
                uint32_t a[4];
                a[0] = lds32(ab + k0); a[1] = lds32(ab + 1024 + k0);
                a[2] = lds32(ab + k1); a[3] = lds32(ab + 1024 + k1);
#pragma unroll
                for (int nf = 0; nf < 8; nf++) {
                    uint32_t b2[2];
                    b2[0] = lds32(bb + (uint32_t)(nf * 1024) + k0);
                    b2[1] = lds32(bb + (uint32_t)(nf * 1024) + k1);
                    mma_bf16(sc[nf], a, b2);
                }
            }
        }

        // ---- causal mask (diagonal tile only) ----
        if (kb == qb) {
#pragma unroll
            for (int nf = 0; nf < 8; nf++)
#pragma unroll
                for (int cc = 0; cc < 4; cc++) {
                    const int jl = nf * 8 + tg * 2 + (cc & 1);
                    const int rl = wr * 16 + g + (cc >> 1) * 8;
                    if (jl > rl) sc[nf][cc] = -1e30f;
                }
        }

        // ---- online softmax per row; write P hi/lo to smem ----
#pragma unroll
        for (int r = 0; r < 2; r++) {
            float mt = -1e30f;
#pragma unroll
            for (int nf = 0; nf < 8; nf++)
                mt = fmaxf(mt, fmaxf(sc[nf][r * 2], sc[nf][r * 2 + 1]));
            mt = fmaxf(mt, __shfl_xor_sync(0xffffffffu, mt, 1));
            mt = fmaxf(mt, __shfl_xor_sync(0xffffffffu, mt, 2));
            const float mn = fmaxf(m2[r], mt);
            const float al = __expf(m2[r] - mn);
            float ls = 0.f;
#pragma unroll
            for (int nf = 0; nf < 8; nf++) {
                float p0 = __expf(sc[nf][r * 2] - mn);
                float p1 = __expf(sc[nf][r * 2 + 1] - mn);
                sc[nf][r * 2] = p0; sc[nf][r * 2 + 1] = p1;
                ls += p0 + p1;
            }
            ls += __shfl_xor_sync(0xffffffffu, ls, 1);
            ls += __shfl_xor_sync(0xffffffffu, ls, 2);
            l2[r] = l2[r] * al + ls;
            m2[r] = mn;
#pragma unroll
            for (int nf = 0; nf < 8; nf++) { o[nf][r * 2] *= al; o[nf][r * 2 + 1] *= al; }

            const uint32_t prow = (uint32_t)(wr * 16 + g + r * 8);
            const uint32_t rsw = (prow & 7) << 4;
#pragma unroll
            for (int nf = 0; nf < 8; nf++) {
                const float p0 = sc[nf][r * 2], p1 = sc[nf][r * 2 + 1];
                __nv_bfloat16 h0, l0, h1, l1;
                split2(p0, h0, l0); split2(p1, h1, l1);
                const uint32_t uh = ((uint32_t)__bfloat16_as_ushort(h1) << 16) | __bfloat16_as_ushort(h0);
                const uint32_t ul = ((uint32_t)__bfloat16_as_ushort(l1) << 16) | __bfloat16_as_ushort(l0);
                const uint32_t off = (prow * 128 + (uint32_t)(nf * 16) + tg4) ^ rsw;
                sts32(sb + APH + off, uh);
                sts32(sb + APL + off, ul);
            }
        }
        __syncwarp();

        // ---- PV: 3 segs x 4 kfrags x 8 nfrags(dk) ----
#pragma unroll
        for (int seg = 0; seg < 3; seg++) {
            const uint32_t ab = sb + ((seg == 1) ? APL : APH) + arow;
            const uint32_t bb = sb + kvoff + 16384u + ((seg == 2) ? 8192u : 0u) + (uint32_t)(g * 128);
#pragma unroll
            for (int kk = 0; kk < 4; kk++) {
                const uint32_t k0 = ((uint32_t)(kk * 32) + tg4) ^ gx;
                const uint32_t k1 = ((uint32_t)(kk * 32 + 16) + tg4) ^ gx;
                uint32_t a[4];
                a[0] = lds32(ab + k0); a[1] = lds32(ab + 1024 + k0);
                a[2] = lds32(ab + k1); a[3] = lds32(ab + 1024 + k1);
#pragma unroll
                for (int nf = 0; nf < 8; nf++) {
                    uint32_t b2[2];
                    b2[0] = lds32(bb + (uint32_t)(nf * 1024) + k0);
                    b2[1] = lds32(bb + (uint32_t)(nf * 1024) + k1);
                    mma_bf16(o[nf], a, b2);
                }
            }
        }
        __syncthreads();
    }

    // ---- epilogue: O/l -> atte (A-side ext) ----
    const float inv[2] = {1.f / l2[0], 1.f / l2[1]};
#pragma unroll
    for (int r = 0; r < 2; r++) {
        const int srow = qb * 64 + wr * 16 + g + r * 8;
        const size_t erb = (size_t)(b_ * 2048 + srow) * 3072;
#pragma unroll
        for (int nf = 0; nf < 8; nf++) {
            const int col = h_ * 64 + nf * 8 + tg * 2;
            store_ext(g_atte, erb, 1024, col,     o[nf][r * 2]     * inv[r]);
            store_ext(g_atte, erb, 1024, col + 1, o[nf][r * 2 + 1] * inv[r]);
        }
    }
}

// ======================= launch ==================================================
extern "C" void kernel_launch(void* const* d_in, const int* in_sizes, int n_in,
                              void* d_out, int out_size)
{
    const float* x  = (const float*)d_in[0];
    const float* Wq = (const float*)d_in[1];
    const float* bq = (const float*)d_in[2];
    const float* Wk = (const float*)d_in[3];
    const float* bk = (const float*)d_in[4];
    const float* Wv = (const float*)d_in[5];
    const float* bv = (const float*)d_in[6];
    const float* Wo = (const float*)d_in[7];
    const float* bo = (const float*)d_in[8];
    const float* W1 = (const float*)d_in[9];
    const float* b1 = (const float*)d_in[10];
    const float* W2 = (const float*)d_in[11];
    const float* b2 = (const float*)d_in[12];
    float* out = (float*)d_out;

    float *x1, *bqkv;
    __nv_bfloat16 *xe, *atte, *x1e, *he, *Wqkve, *Woe, *W1e, *W2e;
    cudaGetSymbolAddress((void**)&x1,    g_x1);
    cudaGetSymbolAddress((void**)&bqkv,  g_bqkv);
    cudaGetSymbolAddress((void**)&xe,    g_xe);
    cudaGetSymbolAddress((void**)&atte,  g_atte);
    cudaGetSymbolAddress((void**)&x1e,   g_x1e);
    cudaGetSymbolAddress((void**)&he,    g_he);
    cudaGetSymbolAddress((void**)&Wqkve, g_Wqkve);
    cudaGetSymbolAddress((void**)&Woe,   g_Woe);
    cudaGetSymbolAddress((void**)&W1e,   g_W1e);
    cudaGetSymbolAddress((void**)&W2e,   g_W2e);

    cudaFuncSetAttribute(tc_gemm<0>, cudaFuncAttributeMaxDynamicSharedMemorySize, GEMM_SMEM);
    cudaFuncSetAttribute(tc_gemm<1>, cudaFuncAttributeMaxDynamicSharedMemorySize, GEMM_SMEM);
    cudaFuncSetAttribute(tc_gemm<2>, cudaFuncAttributeMaxDynamicSharedMemorySize, GEMM_SMEM);
    cudaFuncSetAttribute(tc_gemm<3>, cudaFuncAttributeMaxDynamicSharedMemorySize, GEMM_SMEM);
    cudaFuncSetAttribute(attn_mma, cudaFuncAttributeMaxDynamicSharedMemorySize, ATT_SMEM);

    // conversions
    conv_ext_k<0><<<2048, 256>>>(x,  xe, 10, M_TOT * D_MODEL);
    conv_ext_k<1><<<2048, 256>>>(Wq, Wqkve,                              10, D_MODEL * D_MODEL);
    conv_ext_k<1><<<2048, 256>>>(Wk, Wqkve + (size_t)1024 * 3072,        10, D_MODEL * D_MODEL);
    conv_ext_k<1><<<2048, 256>>>(Wv, Wqkve + (size_t)2048 * 3072,        10, D_MODEL * D_MODEL);
    conv_ext_k<1><<<2048, 256>>>(Wo, Woe, 10, D_MODEL * D_MODEL);
    conv_ext_k<1><<<2048, 256>>>(W1, W1e, 10, FF_DIM_ * D_MODEL);
    conv_ext_k<1><<<2048, 256>>>(W2, W2e, 12, D_MODEL * FF_DIM_);
    concat_bias_k<<<12, 256>>>(bq, bk, bv);

    const dim3 gQKV(3072 / 128, M_TOT / 128);        // (24, 32)
    const dim3 gN1024(D_MODEL / 128, M_TOT / 128);   // (8, 32)
    const dim3 gN4096(FF_DIM_ / 128, M_TOT / 128);   // (32, 32)

    // fused QKV projection -> q/k hi-lo pairs + transposed V
    tc_gemm<0><<<gQKV, 256, GEMM_SMEM>>>(xe, Wqkve, bqkv, nullptr, nullptr, nullptr, 3072, 0);

    attn_mma<<<dim3(SEQ_ / 64, BATCH_ * N_HEADS), 128, ATT_SMEM>>>();

    tc_gemm<1><<<gN1024, 256, GEMM_SMEM>>>(atte, Woe, bo, x, x1, x1e, 3 * D_MODEL, 10);
    tc_gemm<2><<<gN4096, 256, GEMM_SMEM>>>(x1e, W1e, b1, nullptr, nullptr, he, 3 * D_MODEL, 12);
    tc_gemm<3><<<gN1024, 256, GEMM_SMEM>>>(he, W2e, b2, x1, out, nullptr, 3 * FF_DIM_, 0);
}

// round 12
// speedup vs baseline: 5.2707x; 1.6135x over previous
#include <cuda_runtime.h>
#include <cuda_fp16.h>
#include <cstdint>

#define D_MODEL 1024
#define N_HEADS 16
#define HEAD_K  64
#define FF_DIM_ 4096
#define BATCH_  2
#define SEQ_    2048
#define M_TOT   (BATCH_*SEQ_)   // 4096

// ======================= scratch (device globals) =================================
__device__ float g_x1 [(size_t)M_TOT * D_MODEL];   // x + attn_out
// split-fp16 ext operands: A-side [R,2C]=[hi|lo], B-side [R,2C]=[hi|hi]
__device__ __half g_xe  [(size_t)M_TOT * 2 * D_MODEL];
__device__ __half g_atte[(size_t)M_TOT * 2 * D_MODEL];
__device__ __half g_x1e [(size_t)M_TOT * 2 * D_MODEL];
__device__ __half g_he  [(size_t)M_TOT * 2 * FF_DIM_];
__device__ __half g_Wqkve[(size_t)3 * D_MODEL * 2 * D_MODEL];
__device__ __half g_Woe [(size_t)D_MODEL * 2 * D_MODEL];
__device__ __half g_W1e [(size_t)FF_DIM_ * 2 * D_MODEL];
__device__ __half g_W2e [(size_t)D_MODEL * 2 * FF_DIM_];
__device__ float g_bqkv[3 * D_MODEL];
// attention operands. q (A-side) hi/lo, prescaled 0.125. k/v hi only (B-side).
__device__ __half g_qh [(size_t)M_TOT * 64 * N_HEADS];
__device__ __half g_ql [(size_t)M_TOT * 64 * N_HEADS];
__device__ __half g_kh [(size_t)M_TOT * 64 * N_HEADS];
__device__ __half g_vth[(size_t)M_TOT * 64 * N_HEADS];   // [B,H,64,S]

// ======================= helpers ==================================================
__device__ __forceinline__ uint32_t smem_u32(const void* p) {
    uint32_t a;
    asm("{ .reg .u64 t; cvta.to.shared.u64 t, %1; cvt.u32.u64 %0, t; }" : "=r"(a) : "l"(p));
    return a;
}
__device__ __forceinline__ void cp_async16(uint32_t dst, const void* src) {
    asm volatile("cp.async.cg.shared.global [%0], [%1], 16;" :: "r"(dst), "l"(src) : "memory");
}
__device__ __forceinline__ void cp_commit() {
    asm volatile("cp.async.commit_group;" ::: "memory");
}
template<int N> __device__ __forceinline__ void cp_wait() {
    asm volatile("cp.async.wait_group %0;" :: "n"(N) : "memory");
}
__device__ __forceinline__ uint32_t lds32(uint32_t addr) {
    uint32_t v;
    asm volatile("ld.shared.b32 %0, [%1];" : "=r"(v) : "r"(addr));
    return v;
}
__device__ __forceinline__ void sts32(uint32_t addr, uint32_t v) {
    asm volatile("st.shared.b32 [%0], %1;" :: "r"(addr), "r"(v) : "memory");
}
__device__ __forceinline__ void mma_f16(float* c, const uint32_t* a, const uint32_t* b) {
    asm volatile(
        "mma.sync.aligned.m16n8k16.row.col.f32.f16.f16.f32 "
        "{%0,%1,%2,%3}, {%4,%5,%6,%7}, {%8,%9}, {%0,%1,%2,%3};"
        : "+f"(c[0]), "+f"(c[1]), "+f"(c[2]), "+f"(c[3])
        : "r"(a[0]), "r"(a[1]), "r"(a[2]), "r"(a[3]), "r"(b[0]), "r"(b[1]));
}
#define SW128(off) ((off) ^ (((off) >> 3) & 0x70))

__device__ __forceinline__ void split2h(float v, __half& hi, __half& lo) {
    hi = __float2half(v);
    lo = __float2half(v - __half2float(hi));
}

// BSIDE=0: [hi|lo]; BSIDE=1: [hi|hi]
template<int BSIDE>
__global__ void __launch_bounds__(256) conv_ext_k(const float* __restrict__ src,
                                                  __half* __restrict__ dst,
                                                  int lc, int total) {
    const int C = 1 << lc;
    for (int i = blockIdx.x * 256 + threadIdx.x; i < total; i += gridDim.x * 256) {
        const int r = i >> lc, c = i & (C - 1);
        const size_t rb = (size_t)r * 2 * C;
        __half hi, lo; split2h(src[i], hi, lo);
        dst[rb + c] = hi;
        dst[rb + C + c] = BSIDE ? hi : lo;
    }
}

__global__ void __launch_bounds__(256) concat_bias_k(const float* __restrict__ bq,
                                                     const float* __restrict__ bk,
                                                     const float* __restrict__ bv) {
    int i = blockIdx.x * 256 + threadIdx.x;
    if (i < 1024)       g_bqkv[i] = bq[i];
    else if (i < 2048)  g_bqkv[i] = bk[i - 1024];
    else if (i < 3072)  g_bqkv[i] = bv[i - 2048];
}

// ======================= mma.sync fp16 GEMM ======================================
// C[M,N] = A'[M,K2] * B'[N,K2]^T. CTA 128x128, BK=64 halfs, SW128, 3-stage cp.async.
// MODE 0: fused QKV epilogue -> q hi/lo (x0.125), k hi, vt hi (transposed)
// MODE 1: x1 = acc+bias+res; write fp32 + ext[hi|lo]
// MODE 2: h = relu(acc+bias); write ext[hi|lo]
// MODE 3: out = acc+bias+res fp32
#define STAGE_BYTES 32768
#define B_OFF 16384
#define N_STAGES 3
#define GEMM_SMEM (1024 + N_STAGES * STAGE_BYTES)

template<int MODE>
__global__ void __launch_bounds__(256, 1) tc_gemm(
    const __half* __restrict__ Ae, const __half* __restrict__ Be,
    const float* __restrict__ bias, const float* __restrict__ res,
    float* __restrict__ out, __half* __restrict__ oute,
    int K2, int lcout)
{
    extern __shared__ char dsm[];
    const int tid  = threadIdx.x;
    const int wid  = tid >> 5;
    const int lane = tid & 31;
    const int g    = lane >> 2;
    const int tg   = lane & 3;
    const int wm   = wid & 1;
    const int wn   = wid >> 1;
    const uint32_t sb = (smem_u32(dsm) + 1023) & ~1023u;
    const int bm = blockIdx.y << 7;
    const int bn = blockIdx.x << 7;
    const int T  = K2 >> 6;

    float acc[4][4][4];
#pragma unroll
    for (int i = 0; i < 4; i++)
#pragma unroll
        for (int j = 0; j < 4; j++)
#pragma unroll
            for (int r = 0; r < 4; r++) acc[i][j][r] = 0.f;

    auto load_tile = [&](int tile, uint32_t stage) {
        const int k0 = tile << 6;
#pragma unroll
        for (int it = 0; it < 4; it++) {
            const int idx = tid + it * 256;
            const int row = idx >> 3, co = (idx & 7) << 4;
            cp_async16(stage + SW128(row * 128 + co),
                       (const char*)Ae + ((size_t)(bm + row) * K2 + k0) * 2 + co);
        }
#pragma unroll
        for (int it = 0; it < 4; it++) {
            const int idx = tid + it * 256;
            const int row = idx >> 3, co = (idx & 7) << 4;
            cp_async16(stage + B_OFF + SW128(row * 128 + co),
                       (const char*)Be + ((size_t)(bn + row) * K2 + k0) * 2 + co);
        }
        cp_commit();
    };

    load_tile(0, sb);
    load_tile(1, sb + STAGE_BYTES);
    load_tile(2, sb + 2 * STAGE_BYTES);

    const uint32_t gx = (uint32_t)(g << 4);
    const uint32_t tg4 = (uint32_t)(tg << 2);

    for (int t = 0; t < T; t++) {
        cp_wait<2>();
        __syncthreads();
        const uint32_t stage = sb + (uint32_t)(t % N_STAGES) * STAGE_BYTES;
        const uint32_t abase = stage + (uint32_t)(wm * 64 + g) * 128;
        const uint32_t bbase = stage + B_OFF + (uint32_t)(wn * 32 + g) * 128;

#pragma unroll
        for (int kk = 0; kk < 4; kk++) {
            const uint32_t kb0 = ((uint32_t)(kk * 32) + tg4) ^ gx;
            const uint32_t kb1 = ((uint32_t)(kk * 32 + 16) + tg4) ^ gx;
            uint32_t a[4][4], b[4][2];
#pragma unroll
            for (int mi = 0; mi < 4; mi++) {
                const uint32_t r0 = abase + (uint32_t)(mi * 16) * 128;
                a[mi][0] = lds32(r0 + kb0);
                a[mi][1] = lds32(r0 + 8 * 128 + kb0);
                a[mi][2] = lds32(r0 + kb1);
                a[mi][3] = lds32(r0 + 8 * 128 + kb1);
            }
#pragma unroll
            for (int ni = 0; ni < 4; ni++) {
                const uint32_t r0 = bbase + (uint32_t)(ni * 8) * 128;
                b[ni][0] = lds32(r0 + kb0);
                b[ni][1] = lds32(r0 + kb1);
            }
#pragma unroll
            for (int mi = 0; mi < 4; mi++)
#pragma unroll
                for (int ni = 0; ni < 4; ni++)
                    mma_f16(acc[mi][ni], a[mi], b[ni]);
        }
        __syncthreads();
        if (t + 3 < T) load_tile(t + 3, stage);
    }

    // ---- epilogue ----
#pragma unroll
    for (int mi = 0; mi < 4; mi++) {
        const int r0 = bm + wm * 64 + mi * 16 + g;
#pragma unroll
        for (int rr = 0; rr < 2; rr++) {
            const int grow = r0 + rr * 8;
#pragma unroll
            for (int ni = 0; ni < 4; ni++) {
                const int gcol = bn + wn * 32 + ni * 8 + tg * 2;
                float v0 = acc[mi][ni][rr * 2 + 0] + bias[gcol];
                float v1 = acc[mi][ni][rr * 2 + 1] + bias[gcol + 1];

                if (MODE == 0) {
                    const int b_ = grow >> 11, s = grow & 2047;
                    if (gcol < 1024) {          // Q (x0.125) -> hi/lo
                        const int h = gcol >> 6, dk = gcol & 63;
                        const size_t idx = ((size_t)(b_ * 16 + h) * 2048 + s) * 64 + dk;
                        __half h0, l0, h1, l1;
                        split2h(v0 * 0.125f, h0, l0);
                        split2h(v1 * 0.125f, h1, l1);
                        *(__half2*)(g_qh + idx) = __halves2half2(h0, h1);
                        *(__half2*)(g_ql + idx) = __halves2half2(l0, l1);
                    } else if (gcol < 2048) {   // K -> hi only
                        const int lc = gcol - 1024;
                        const int h = lc >> 6, dk = lc & 63;
                        const size_t idx = ((size_t)(b_ * 16 + h) * 2048 + s) * 64 + dk;
                        *(__half2*)(g_kh + idx) =
                            __halves2half2(__float2half(v0), __float2half(v1));
                    } else {                    // V transposed [B,H,64,S] -> hi only
                        const int lc = gcol - 2048;
                        const int h = lc >> 6, dk = lc & 63;
                        const size_t idx = ((size_t)(b_ * 16 + h) * 64 + dk) * 2048 + s;
                        g_vth[idx]        = __float2half(v0);
                        g_vth[idx + 2048] = __float2half(v1);
                    }
                } else if (MODE == 1) {
                    const size_t rb = (size_t)grow * 1024 + gcol;
                    const float2 rv = *(const float2*)(res + rb);
                    v0 += rv.x; v1 += rv.y;
                    *(float2*)(out + rb) = make_float2(v0, v1);
                    const int C = 1 << lcout;
                    const size_t erb = (size_t)grow * 2 * C;
                    __half h0, l0, h1, l1;
                    split2h(v0, h0, l0); split2h(v1, h1, l1);
                    *(__half2*)(oute + erb + gcol)     = __halves2half2(h0, h1);
                    *(__half2*)(oute + erb + C + gcol) = __halves2half2(l0, l1);
                } else if (MODE == 2) {
                    const int C = 1 << lcout;
                    const size_t erb = (size_t)grow * 2 * C;
                    __half h0, l0, h1, l1;
                    split2h(fmaxf(v0, 0.f), h0, l0);
                    split2h(fmaxf(v1, 0.f), h1, l1);
                    *(__half2*)(oute + erb + gcol)     = __halves2half2(h0, h1);
                    *(__half2*)(oute + erb + C + gcol) = __halves2half2(l0, l1);
                } else {
                    const size_t rb = (size_t)grow * 1024 + gcol;
                    const float2 rv = *(const float2*)(res + rb);
                    *(float2*)(out + rb) = make_float2(v0 + rv.x, v1 + rv.y);
                }
            }
        }
    }
}

// ======================= tensor-core causal flash attention ======================
// 128 threads, 4 warps x 16 q-rows. 64-key tiles, double-buffered cp.async.
// Scores: segs {(Qh,Kh),(Ql,Kh)}; PV: segs {(Ph,Vh),(Pl,Vh)}.
#define AQH 0
#define AQL 8192
#define AKV0 16384          // Kh 8KB + Vh 8KB
#define AKV1 32768
#define APH 49152
#define APL 57344
#define ATT_SMEM 65536

__global__ void __launch_bounds__(128) attn_mma()
{
    extern __shared__ char sm[];
    const uint32_t sb = smem_u32(sm);
    const int tid = threadIdx.x;
    const int wr  = tid >> 5;
    const int lane = tid & 31;
    const int g  = lane >> 2;
    const int tg = lane & 3;
    const uint32_t gx = (uint32_t)(g << 4);
    const uint32_t tg4 = (uint32_t)(tg << 2);
    const int qb = blockIdx.x, bh = blockIdx.y;
    const int b_ = bh >> 4, h_ = bh & 15;

    const size_t qkb = (size_t)bh * 2048 * 64;
    const __half* qh = g_qh + qkb + (size_t)qb * 4096;
    const __half* ql = g_ql + qkb + (size_t)qb * 4096;
    const __half* kh = g_kh + qkb;
    const __half* vth = g_vth + (size_t)bh * 64 * 2048;

    auto ld_contig = [&](uint32_t dst, const __half* src) {
#pragma unroll
        for (int it = 0; it < 4; it++) {
            const int c = tid + it * 128;
            const int row = c >> 3, co = (c & 7) << 4;
            cp_async16(dst + SW128(row * 128 + co), (const char*)src + c * 16);
        }
    };
    auto ld_vt = [&](uint32_t dst, const __half* src) {
#pragma unroll
        for (int it = 0; it < 4; it++) {
            const int c = tid + it * 128;
            const int row = c >> 3, co = (c & 7) << 4;
            cp_async16(dst + SW128(row * 128 + co),
                       (const char*)(src + (size_t)row * 2048) + co);
        }
    };
    auto load_kv = [&](int kb, uint32_t off) {
        ld_contig(sb + off,        kh + (size_t)kb * 4096);
        ld_vt    (sb + off + 8192, vth + (size_t)kb * 64);
    };

    ld_contig(sb + AQH, qh);
    ld_contig(sb + AQL, ql);
    load_kv(0, AKV0);
    cp_commit();

    float m2[2] = {-1e30f, -1e30f}, l2[2] = {0.f, 0.f};
    float o[8][4];
#pragma unroll
    for (int i = 0; i < 8; i++)
#pragma unroll
        for (int j = 0; j < 4; j++) o[i][j] = 0.f;

    const uint32_t arow = (uint32_t)(wr * 16 + g) * 128;

    for (int kb = 0; kb <= qb; kb++) {
        const uint32_t kvoff = (kb & 1) ? AKV1 : AKV0;
        if (kb < qb) {
            load_kv(kb + 1, (kb & 1) ? AKV0 : AKV1);
            cp_commit();
            cp_wait<1>();
        } else {
            cp_wait<0>();
        }
        __syncthreads();

        // ---- scores: 2 segs x 4 kfrags x 8 nfrags ----
        float sc[8][4];
#pragma unroll
        for (int i = 0; i < 8; i++)
#pragma unroll
            for (int j = 0; j < 4; j++) sc[i][j] = 0.f;

#pragma unroll
        for (int seg = 0; seg < 2; seg++) {
            const uint32_t ab = sb + (seg ? AQL : AQH) + arow;
            const uint32_t bb = sb + kvoff + (uint32_t)(g * 128);
#pragma unroll
            for (int kk = 0; kk < 4; kk++) {
                const uint32_t k0 = ((uint32_t)(kk * 32) + tg4) ^ gx;
                const uint32_t k1 = ((uint32_t)(kk * 32 + 16) + tg4) ^ gx;
                uint32_t a[4];
                a[0] = lds32(ab + k0); a[1] = lds32(ab + 1024 + k0);
                a[2] = lds32(ab + k1); a[3] = lds32(ab + 1024 + k1);
#pragma unroll
                for (int nf = 0; nf < 8; nf++) {
                    uint32_t b2[2];
                    b2[0] = lds32(bb + (uint32_t)(nf * 1024) + k0);
                    b2[1] = lds32(bb + (uint32_t)(nf * 1024) + k1);
                    mma_f16(sc[nf], a, b2);
                }
            }
        }

        // ---- causal mask (diagonal tile only) ----
        if (kb == qb) {
#pragma unroll
            for (int nf = 0; nf < 8; nf++)
#pragma unroll
                for (int cc = 0; cc < 4; cc++) {
                    const int jl = nf * 8 + tg * 2 + (cc & 1);
                    const int rl = wr * 16 + g + (cc >> 1) * 8;
                    if (jl > rl) sc[nf][cc] = -1e30f;
                }
        }

        // ---- online softmax per row; write P hi/lo to smem ----
#pragma unroll
        for (int r = 0; r < 2; r++) {
            float mt = -1e30f;
#pragma unroll
            for (int nf = 0; nf < 8; nf++)
                mt = fmaxf(mt, fmaxf(sc[nf][r * 2], sc[nf][r * 2 + 1]));
            mt = fmaxf(mt, __shfl_xor_sync(0xffffffffu, mt, 1));
            mt = fmaxf(mt, __shfl_xor_sync(0xffffffffu, mt, 2));
            const float mn = fmaxf(m2[r], mt);
            const float al = __expf(m2[r] - mn);
            float ls = 0.f;
#pragma unroll
            for (int nf = 0; nf < 8; nf++) {
                float p0 = __expf(sc[nf][r * 2] - mn);
                float p1 = __expf(sc[nf][r * 2 + 1] - mn);
                sc[nf][r * 2] = p0; sc[nf][r * 2 + 1] = p1;
                ls += p0 + p1;
            }
            ls += __shfl_xor_sync(0xffffffffu, ls, 1);
            ls += __shfl_xor_sync(0xffffffffu, ls, 2);
            l2[r] = l2[r] * al + ls;
            m2[r] = mn;
#pragma unroll
            for (int nf = 0; nf < 8; nf++) { o[nf][r * 2] *= al; o[nf][r * 2 + 1] *= al; }

            const uint32_t prow = (uint32_t)(wr * 16 + g + r * 8);
            const uint32_t rsw = (prow & 7) << 4;
#pragma unroll
            for (int nf = 0; nf < 8; nf++) {
                __half h0, l0, h1, l1;
                split2h(sc[nf][r * 2], h0, l0);
                split2h(sc[nf][r * 2 + 1], h1, l1);
                const uint32_t uh = ((uint32_t)__half_as_ushort(h1) << 16) | __half_as_ushort(h0);
                const uint32_t ul = ((uint32_t)__half_as_ushort(l1) << 16) | __half_as_ushort(l0);
                const uint32_t off = (prow * 128 + (uint32_t)(nf * 16) + tg4) ^ rsw;
                sts32(sb + APH + off, uh);
                sts32(sb + APL + off, ul);
            }
        }
        __syncwarp();

        // ---- PV: 2 segs x 4 kfrags x 8 nfrags(dk) ----
#pragma unroll
        for (int seg = 0; seg < 2; seg++) {
            const uint32_t ab = sb + (seg ? APL : APH) + arow;
            const uint32_t bb = sb + kvoff + 8192u + (uint32_t)(g * 128);
#pragma unroll
            for (int kk = 0; kk < 4; kk++) {
                const uint32_t k0 = ((uint32_t)(kk * 32) + tg4) ^ gx;
                const uint32_t k1 = ((uint32_t)(kk * 32 + 16) + tg4) ^ gx;
                uint32_t a[4];
                a[0] = lds32(ab + k0); a[1] = lds32(ab + 1024 + k0);
                a[2] = lds32(ab + k1); a[3] = lds32(ab + 1024 + k1);
#pragma unroll
                for (int nf = 0; nf < 8; nf++) {
                    uint32_t b2[2];
                    b2[0] = lds32(bb + (uint32_t)(nf * 1024) + k0);
                    b2[1] = lds32(bb + (uint32_t)(nf * 1024) + k1);
                    mma_f16(o[nf], a, b2);
                }
            }
        }
        __syncthreads();
    }

    // ---- epilogue: O/l -> atte (A-side ext [hi|lo], C=1024) ----
    const float inv[2] = {1.f / l2[0], 1.f / l2[1]};
#pragma unroll
    for (int r = 0; r < 2; r++) {
        const int srow = qb * 64 + wr * 16 + g + r * 8;
        const size_t erb = (size_t)(b_ * 2048 + srow) * 2048;
#pragma unroll
        for (int nf = 0; nf < 8; nf++) {
            const int col = h_ * 64 + nf * 8 + tg * 2;
            __half h0, l0, h1, l1;
            split2h(o[nf][r * 2]     * inv[r], h0, l0);
            split2h(o[nf][r * 2 + 1] * inv[r], h1, l1);
            *(__half2*)(g_atte + erb + col)        = __halves2half2(h0, h1);
            *(__half2*)(g_atte + erb + 1024 + col) = __halves2half2(l0, l1);
        }
    }
}

// ======================= launch ==================================================
extern "C" void kernel_launch(void* const* d_in, const int* in_sizes, int n_in,
                              void* d_out, int out_size)
{
    const float* x  = (const float*)d_in[0];
    const float* Wq = (const float*)d_in[1];
    const float* bq = (const float*)d_in[2];
    const float* Wk = (const float*)d_in[3];
    const float* bk = (const float*)d_in[4];
    const float* Wv = (const float*)d_in[5];
    const float* bv = (const float*)d_in[6];
    const float* Wo = (const float*)d_in[7];
    const float* bo = (const float*)d_in[8];
    const float* W1 = (const float*)d_in[9];
    const float* b1 = (const float*)d_in[10];
    const float* W2 = (const float*)d_in[11];
    const float* b2 = (const float*)d_in[12];
    float* out = (float*)d_out;

    float *x1, *bqkv;
    __half *xe, *atte, *x1e, *he, *Wqkve, *Woe, *W1e, *W2e;
    cudaGetSymbolAddress((void**)&x1,    g_x1);
    cudaGetSymbolAddress((void**)&bqkv,  g_bqkv);
    cudaGetSymbolAddress((void**)&xe,    g_xe);
    cudaGetSymbolAddress((void**)&atte,  g_atte);
    cudaGetSymbolAddress((void**)&x1e,   g_x1e);
    cudaGetSymbolAddress((void**)&he,    g_he);
    cudaGetSymbolAddress((void**)&Wqkve, g_Wqkve);
    cudaGetSymbolAddress((void**)&Woe,   g_Woe);
    cudaGetSymbolAddress((void**)&W1e,   g_W1e);
    cudaGetSymbolAddress((void**)&W2e,   g_W2e);

    cudaFuncSetAttribute(tc_gemm<0>, cudaFuncAttributeMaxDynamicSharedMemorySize, GEMM_SMEM);
    cudaFuncSetAttribute(tc_gemm<1>, cudaFuncAttributeMaxDynamicSharedMemorySize, GEMM_SMEM);
    cudaFuncSetAttribute(tc_gemm<2>, cudaFuncAttributeMaxDynamicSharedMemorySize, GEMM_SMEM);
    cudaFuncSetAttribute(tc_gemm<3>, cudaFuncAttributeMaxDynamicSharedMemorySize, GEMM_SMEM);
    cudaFuncSetAttribute(attn_mma, cudaFuncAttributeMaxDynamicSharedMemorySize, ATT_SMEM);

    // conversions (ext width 2C)
    conv_ext_k<0><<<2048, 256>>>(x,  xe, 10, M_TOT * D_MODEL);
    conv_ext_k<1><<<2048, 256>>>(Wq, Wqkve,                       10, D_MODEL * D_MODEL);
    conv_ext_k<1><<<2048, 256>>>(Wk, Wqkve + (size_t)1024 * 2048, 10, D_MODEL * D_MODEL);
    conv_ext_k<1><<<2048, 256>>>(Wv, Wqkve + (size_t)2048 * 2048, 10, D_MODEL * D_MODEL);
    conv_ext_k<1><<<2048, 256>>>(Wo, Woe, 10, D_MODEL * D_MODEL);
    conv_ext_k<1><<<2048, 256>>>(W1, W1e, 10, FF_DIM_ * D_MODEL);
    conv_ext_k<1><<<2048, 256>>>(W2, W2e, 12, D_MODEL * FF_DIM_);
    concat_bias_k<<<12, 256>>>(bq, bk, bv);

    const dim3 gQKV(3072 / 128, M_TOT / 128);        // (24, 32)
    const dim3 gN1024(D_MODEL / 128, M_TOT / 128);   // (8, 32)
    const dim3 gN4096(FF_DIM_ / 128, M_TOT / 128);   // (32, 32)

    // fused QKV projection
    tc_gemm<0><<<gQKV, 256, GEMM_SMEM>>>(xe, Wqkve, bqkv, nullptr, nullptr, nullptr, 2048, 0);

    attn_mma<<<dim3(SEQ_ / 64, BATCH_ * N_HEADS), 128, ATT_SMEM>>>();

    tc_gemm<1><<<gN1024, 256, GEMM_SMEM>>>(atte, Woe, bo, x, x1, x1e, 2048, 10);
    tc_gemm<2><<<gN4096, 256, GEMM_SMEM>>>(x1e, W1e, b1, nullptr, nullptr, he, 2048, 12);
    tc_gemm<3><<<gN1024, 256, GEMM_SMEM>>>(he, W2e, b2, x1, out, nullptr, 2 * FF_DIM_, 0);
}